// round 9
// baseline (speedup 1.0000x reference)
#include <cuda_runtime.h>

#define SQ    2048
#define BATCH 64
#define IDIM  256
#define HDIM  512
#define EDIM  256
#define BH    (BATCH * HDIM)    // 32768 floats per timestep

typedef unsigned long long ull;

// Persistent scratch (1MB + 2KB) as __device__ globals (no allocs allowed).
__device__ float g_Whh[HDIM * HDIM];   // W_hh[i][j] = sum_e Wm[i][e] * We[e][j]
__device__ float g_c[HDIM];            // c[i] = sum_e Wm[i][e] * be[e]

// Packed f32x2 FMA (sm_103a): 2x MACs per issue vs scalar FFMA.
__device__ __forceinline__ ull ffma2(ull a, ull b, ull c) {
    ull d;
    asm("fma.rn.f32x2 %0, %1, %2, %3;" : "=l"(d) : "l"(a), "l"(b), "l"(c));
    return d;
}
__device__ __forceinline__ float2 unpack2(ull v) {
    float2 r;
    asm("mov.b64 {%0, %1}, %2;" : "=f"(r.x), "=f"(r.y) : "l"(v));
    return r;
}

// FMA-only rational tanh (no MUFU), abs err ~1e-6 (validated: rel 6.5e-7).
__device__ __forceinline__ float fast_tanh(float x) {
    const float c = 7.90531110763549805f;
    x = fmaxf(-c, fminf(c, x));
    float x2 = x * x;
    float p = -2.76076847742355e-16f;
    p = fmaf(p, x2, 2.00018790482477e-13f);
    p = fmaf(p, x2, -8.60467152213735e-11f);
    p = fmaf(p, x2, 5.12229709037114e-08f);
    p = fmaf(p, x2, 1.48572235717979e-05f);
    p = fmaf(p, x2, 6.37261928875436e-04f);
    p = fmaf(p, x2, 4.89352455891786e-03f);
    p = x * p;
    float q = 1.19825839466702e-06f;
    q = fmaf(q, x2, 1.18534705686654e-04f);
    q = fmaf(q, x2, 2.26843463243900e-03f);
    q = fmaf(q, x2, 4.89352518554385e-03f);
    float r = __uint_as_float(0x7EF311C3u - __float_as_uint(q));
    r = r * fmaf(-q, r, 2.0f);
    r = r * fmaf(-q, r, 2.0f);
    r = r * fmaf(-q, r, 2.0f);
    return p * r;
}

// ---------------------------------------------------------------------------
// Kernel 0: W_hh = Wm @ We  (Wm = Wih[:,256:512]) and c = Wm @ be.
// ---------------------------------------------------------------------------
__global__ void prep_whh_kernel(const float* __restrict__ Wih,
                                const float* __restrict__ We,
                                const float* __restrict__ be) {
    int i = blockIdx.x, tid = threadIdx.x;
    const float* wm = Wih + (size_t)i * 512 + IDIM;   // Wm row i (256 wide)
    float4 acc = make_float4(0.f, 0.f, 0.f, 0.f);
    float cacc = 0.f;
    #pragma unroll 4
    for (int e = 0; e < EDIM; ++e) {
        float a  = __ldg(wm + e);
        float4 b = __ldg((const float4*)(We + (size_t)e * HDIM) + tid);
        acc.x = fmaf(a, b.x, acc.x);
        acc.y = fmaf(a, b.y, acc.y);
        acc.z = fmaf(a, b.z, acc.z);
        acc.w = fmaf(a, b.w, acc.w);
        cacc  = fmaf(a, __ldg(be + e), cacc);
    }
    ((float4*)(g_Whh + (size_t)i * 512))[tid] = acc;
    if (tid == 0) g_c[i] = cacc;
}

// ---------------------------------------------------------------------------
// Kernel 1: stage U[t] into out[t]:
//   t>0 : U = x_t @ Wx^T + b_ih + c       (c folds be @ Wm^T; m-lag substitution)
//   t==0: U = x_0 @ Wx^T + m_0 @ Wm^T + b_ih   (full pre-activation)
// CTA tile: 32 rows x 64 cols, K=256 per pass.  256 thr = 16 colg x 16 kg.
// ---------------------------------------------------------------------------
__global__ void __launch_bounds__(256, 2)
precompute_u_kernel(const float* __restrict__ x,
                    const float* __restrict__ m0,
                    const float* __restrict__ Wih,
                    const float* __restrict__ bih,
                    float* __restrict__ out) {
    extern __shared__ float sm1[];
    float* act  = sm1;                 // [32][256]
    float* part = sm1 + 32 * 256;      // [8 rows][8 ksets][64 cols]

    const int tid = threadIdx.x;
    const int cg  = tid & 15;
    const int kg  = tid >> 4;
    const int t   = blockIdx.y;
    const int colt = blockIdx.x & 7, rowg = blockIdx.x >> 3;
    const int colbase = colt * 64, rowbase = rowg * 32;

    float sreg[8];
    #pragma unroll
    for (int i = 0; i < 8; ++i) sreg[i] = 0.f;

    const int npass = (t == 0) ? 2 : 1;
    for (int pass = 0; pass < npass; ++pass) {
        ull w[4][8];
        const int koff = pass ? IDIM : 0;
        #pragma unroll
        for (int c = 0; c < 4; ++c) {
            const ulonglong2* wp = (const ulonglong2*)
                (Wih + (size_t)(colbase + cg * 4 + c) * 512 + koff + kg * 16);
            #pragma unroll
            for (int j2 = 0; j2 < 4; ++j2) {
                ulonglong2 v = wp[j2];
                w[c][2 * j2]     = v.x;
                w[c][2 * j2 + 1] = v.y;
            }
        }
        const float* src = pass ? (m0 + (size_t)rowbase * EDIM)
                                : (x + ((size_t)t * BATCH + rowbase) * IDIM);
        __syncthreads();
        #pragma unroll
        for (int i = 0; i < 8; ++i)
            ((float4*)act)[tid + i * 256] = __ldg((const float4*)src + tid + i * 256);
        __syncthreads();

        for (int chunk = 0; chunk < 4; ++chunk) {
            #pragma unroll
            for (int b = 0; b < 8; ++b) {
                const ulonglong2* ap =
                    (const ulonglong2*)(act + (chunk * 8 + b) * 256 + kg * 16);
                ull acc[4] = {0ull, 0ull, 0ull, 0ull};
                #pragma unroll
                for (int j2 = 0; j2 < 4; ++j2) {
                    ulonglong2 v = ap[j2];
                    #pragma unroll
                    for (int c = 0; c < 4; ++c) {
                        acc[c] = ffma2(w[c][2 * j2],     v.x, acc[c]);
                        acc[c] = ffma2(w[c][2 * j2 + 1], v.y, acc[c]);
                    }
                }
                float4 r; float2 f;
                f = unpack2(acc[0]); r.x = f.x + f.y;
                f = unpack2(acc[1]); r.y = f.x + f.y;
                f = unpack2(acc[2]); r.z = f.x + f.y;
                f = unpack2(acc[3]); r.w = f.x + f.y;
                r.x += __shfl_xor_sync(0xffffffffu, r.x, 16);
                r.y += __shfl_xor_sync(0xffffffffu, r.y, 16);
                r.z += __shfl_xor_sync(0xffffffffu, r.z, 16);
                r.w += __shfl_xor_sync(0xffffffffu, r.w, 16);
                if (!(kg & 1))
                    ((float4*)part)[(b * 8 + (kg >> 1)) * 16 + cg] = r;
            }
            __syncthreads();
            #pragma unroll
            for (int h = 0; h < 2; ++h) {
                int o = tid + h * 256;
                int r = o >> 6, cc = o & 63;
                float s = 0.f;
                #pragma unroll
                for (int k = 0; k < 8; ++k) s += part[(r * 8 + k) * 64 + cc];
                sreg[chunk * 2 + h] += s;
            }
            __syncthreads();
        }
    }
    #pragma unroll
    for (int chunk = 0; chunk < 4; ++chunk) {
        #pragma unroll
        for (int h = 0; h < 2; ++h) {
            int o = tid + h * 256;
            int r = o >> 6, cc = o & 63;
            int col = colbase + cc;
            float bias = __ldg(bih + col) + ((t > 0) ? g_c[col] : 0.f);
            out[(size_t)t * BH + (size_t)(rowbase + chunk * 8 + r) * HDIM + col]
                = sreg[chunk * 2 + h] + bias;
        }
    }
}

// ---------------------------------------------------------------------------
// Kernel 2: sequential recurrence, 1024 supersteps + fused tails.
//   H[t] = tanh(U[t] + H[t-2] @ W_hh^T),  lag source at t=p,s=0 is h0 (t=1)
//   or nothing (t=0: U[0] is the full pre-activation).
// 16 independent 8-CTA clusters: cluster = (parity, batch-group-of-8).
// CTA: 8 rows x 64 cols, K=512.  512 thr = 16 colg (RC=4) x 32 kg (KT=16)
//   -> 64 weight regs/thread (no spill), 4 warps/SMSP (latency hiding).
// H[t] overwrites U[t] in-place in `out`. Sync = barrier.cluster, next-U
// prefetch in the arrive->wait gap. One output/thread epilogue.
// Tails: h_T in last epilogue (p=1); m_T by p=0 clusters after final barrier.
// ---------------------------------------------------------------------------
__global__ void __launch_bounds__(512, 1) __cluster_dims__(8, 1, 1)
rnn_seq_kernel(const float* __restrict__ h0,
               const float* __restrict__ We,
               const float* __restrict__ be,
               float* __restrict__ out, int write_ht, int write_mt) {
    __shared__ float act [8 * 512];          // 16KB
    __shared__ float part[8 * 16 * 64];      // 32KB

    const int tid = threadIdx.x;
    const int cg  = tid & 15;                // col group: RC=4 cols
    const int kg  = tid >> 4;                // 0..31, KT=16
    const int colt = blockIdx.x;             // 0..7 = cluster rank
    const int grp  = blockIdx.y;             // 0..15
    const int p    = grp >> 3;               // parity
    const int b0   = (grp & 7) * 8;          // batch base
    const int colbase = colt * 64;

    // W_hh slice: 4 cols x 16 k = 32 ull = 64 regs, reused 1024x.
    ull w[4][8];
    #pragma unroll
    for (int c = 0; c < 4; ++c) {
        const ulonglong2* wp = (const ulonglong2*)
            (g_Whh + (size_t)(colbase + cg * 4 + c) * 512 + kg * 16);
        #pragma unroll
        for (int j2 = 0; j2 < 4; ++j2) {
            ulonglong2 v = wp[j2];
            w[c][2 * j2]     = v.x;
            w[c][2 * j2 + 1] = v.y;
        }
    }

    const int r0 = tid >> 6, c0 = tid & 63;  // one output per thread
    const size_t a0 = (size_t)(b0 + r0) * HDIM + colbase + c0;

    int t = p;
    float u0 = out[(size_t)t * BH + a0];     // prefetch U[t]

    for (int s = 0; s < 1024; ++s, t += 2) {
        const bool do_gemm = (s > 0) || (p == 1);
        if (do_gemm) {
            // stage lagged H (8 rows x 512): peers wrote it last superstep
            const float* src = (s == 0) ? (h0 + (size_t)b0 * HDIM)
                                        : (out + (size_t)(t - 2) * BH + (size_t)b0 * HDIM);
            ((float4*)act)[tid]       = __ldcg((const float4*)src + tid);
            ((float4*)act)[tid + 512] = __ldcg((const float4*)src + tid + 512);
            __syncthreads();

            #pragma unroll
            for (int b = 0; b < 8; ++b) {
                const ulonglong2* ap = (const ulonglong2*)(act + b * 512 + kg * 16);
                ull acc[4] = {0ull, 0ull, 0ull, 0ull};
                #pragma unroll
                for (int j2 = 0; j2 < 4; ++j2) {
                    ulonglong2 v = ap[j2];
                    #pragma unroll
                    for (int c = 0; c < 4; ++c) {
                        acc[c] = ffma2(w[c][2 * j2],     v.x, acc[c]);
                        acc[c] = ffma2(w[c][2 * j2 + 1], v.y, acc[c]);
                    }
                }
                float4 r; float2 f;
                f = unpack2(acc[0]); r.x = f.x + f.y;
                f = unpack2(acc[1]); r.y = f.x + f.y;
                f = unpack2(acc[2]); r.z = f.x + f.y;
                f = unpack2(acc[3]); r.w = f.x + f.y;
                r.x += __shfl_xor_sync(0xffffffffu, r.x, 16);
                r.y += __shfl_xor_sync(0xffffffffu, r.y, 16);
                r.z += __shfl_xor_sync(0xffffffffu, r.z, 16);
                r.w += __shfl_xor_sync(0xffffffffu, r.w, 16);
                if (!(kg & 1))
                    ((float4*)part)[(b * 16 + (kg >> 1)) * 16 + cg] = r;
            }
            __syncthreads();
        }

        float sv = u0;
        if (do_gemm) {
            #pragma unroll
            for (int k = 0; k < 16; ++k) sv += part[(r0 * 16 + k) * 64 + c0];
        }
        float hv = fast_tanh(sv);
        out[(size_t)t * BH + a0] = hv;
        if (p == 1 && s == 1023 && write_ht)
            out[(size_t)SQ * BH + a0] = hv;    // h_T = H[2047]

        // cluster barrier: release H[t], prefetch U[t+2] in the gap, acquire.
        // (barrier.cluster is a full block barrier too: no extra syncthreads.)
        asm volatile("barrier.cluster.arrive.aligned;" ::: "memory");
        if (s < 1023) u0 = out[(size_t)(t + 2) * BH + a0];
        asm volatile("barrier.cluster.wait.aligned;" ::: "memory");
    }

    // m_T = H[2046] @ We^T + be  (parity-0 clusters; H[2046] visible post-barrier)
    if (p == 0 && write_mt) {
        const float* src = out + (size_t)(SQ - 2) * BH + (size_t)b0 * HDIM;
        ((float4*)act)[tid]       = __ldcg((const float4*)src + tid);
        ((float4*)act)[tid + 512] = __ldcg((const float4*)src + tid + 512);
        __syncthreads();
        if (tid < 256) {
            int b = tid >> 5, e = colt * 32 + (tid & 31);
            float acc = __ldg(be + e);
            const float4* wr = (const float4*)(We + (size_t)e * HDIM);
            const float* hp = act + b * 512;
            #pragma unroll 4
            for (int j4 = 0; j4 < 128; ++j4) {
                float4 wv = __ldg(wr + j4);
                acc = fmaf(wv.x, hp[j4 * 4 + 0], acc);
                acc = fmaf(wv.y, hp[j4 * 4 + 1], acc);
                acc = fmaf(wv.z, hp[j4 * 4 + 2], acc);
                acc = fmaf(wv.w, hp[j4 * 4 + 3], acc);
            }
            out[(size_t)SQ * BH + (size_t)BATCH * HDIM
                + (size_t)(b0 + b) * EDIM + e] = acc;
        }
    }
}

extern "C" void kernel_launch(void* const* d_in, const int* in_sizes, int n_in,
                              void* d_out, int out_size) {
    const float* x   = (const float*)d_in[0];  // input_seq [S,B,I]
    const float* h0  = (const float*)d_in[1];  // h_0 [B,H]
    const float* m0  = (const float*)d_in[2];  // m_0 [B,E]
    const float* We  = (const float*)d_in[3];  // W_embed [E,H]
    const float* be  = (const float*)d_in[4];  // b_embed [E]
    const float* Wih = (const float*)d_in[5];  // W_ih [H,I+E]
    const float* bih = (const float*)d_in[6];  // b_ih [H]
    float* out = (float*)d_out;

    long long seq_elems = (long long)SQ * BH;
    int write_ht = (out_size >= seq_elems + (long long)BATCH * HDIM) ? 1 : 0;
    int write_mt = (out_size >= seq_elems + (long long)BATCH * HDIM
                                + (long long)BATCH * EDIM) ? 1 : 0;

    // 0) W_hh = Wm @ We, c = Wm @ be
    prep_whh_kernel<<<HDIM, 128>>>(Wih, We, be);
    // 1) U[t] -> out[t] for all t (fully parallel)
    precompute_u_kernel<<<dim3(16, SQ), 256, 49152>>>(x, m0, Wih, bih, out);
    // 2) recurrence: 16 independent 8-CTA clusters, 1024 supersteps (+tails)
    rnn_seq_kernel<<<dim3(8, 16), 512>>>(h0, We, be, out, write_ht, write_mt);
}

// round 10
// speedup vs baseline: 1.1218x; 1.1218x over previous
#include <cuda_runtime.h>

#define SQ    2048
#define BATCH 64
#define IDIM  256
#define HDIM  512
#define EDIM  256
#define BH    (BATCH * HDIM)    // 32768 floats per timestep

typedef unsigned long long ull;

// Persistent scratch (1MB + 2KB) as __device__ globals (no allocs allowed).
__device__ float g_Whh[HDIM * HDIM];   // W_hh[i][j] = sum_e Wm[i][e] * We[e][j]
__device__ float g_c[HDIM];            // c[i] = sum_e Wm[i][e] * be[e]

// Packed f32x2 FMA (sm_103a): 2x MACs per issue vs scalar FFMA.
__device__ __forceinline__ ull ffma2(ull a, ull b, ull c) {
    ull d;
    asm("fma.rn.f32x2 %0, %1, %2, %3;" : "=l"(d) : "l"(a), "l"(b), "l"(c));
    return d;
}
__device__ __forceinline__ float2 unpack2(ull v) {
    float2 r;
    asm("mov.b64 {%0, %1}, %2;" : "=f"(r.x), "=f"(r.y) : "l"(v));
    return r;
}

// FMA-only rational tanh (no MUFU), abs err ~1e-6 (validated: rel 6.5e-7).
__device__ __forceinline__ float fast_tanh(float x) {
    const float c = 7.90531110763549805f;
    x = fmaxf(-c, fminf(c, x));
    float x2 = x * x;
    float p = -2.76076847742355e-16f;
    p = fmaf(p, x2, 2.00018790482477e-13f);
    p = fmaf(p, x2, -8.60467152213735e-11f);
    p = fmaf(p, x2, 5.12229709037114e-08f);
    p = fmaf(p, x2, 1.48572235717979e-05f);
    p = fmaf(p, x2, 6.37261928875436e-04f);
    p = fmaf(p, x2, 4.89352455891786e-03f);
    p = x * p;
    float q = 1.19825839466702e-06f;
    q = fmaf(q, x2, 1.18534705686654e-04f);
    q = fmaf(q, x2, 2.26843463243900e-03f);
    q = fmaf(q, x2, 4.89352518554385e-03f);
    float r = __uint_as_float(0x7EF311C3u - __float_as_uint(q));
    r = r * fmaf(-q, r, 2.0f);
    r = r * fmaf(-q, r, 2.0f);
    r = r * fmaf(-q, r, 2.0f);
    return p * r;
}

// ---------------------------------------------------------------------------
// Kernel 0: W_hh = Wm @ We  (Wm = Wih[:,256:512]) and c = Wm @ be.
// ---------------------------------------------------------------------------
__global__ void prep_whh_kernel(const float* __restrict__ Wih,
                                const float* __restrict__ We,
                                const float* __restrict__ be) {
    int i = blockIdx.x, tid = threadIdx.x;
    const float* wm = Wih + (size_t)i * 512 + IDIM;   // Wm row i (256 wide)
    float4 acc = make_float4(0.f, 0.f, 0.f, 0.f);
    float cacc = 0.f;
    #pragma unroll 8
    for (int e = 0; e < EDIM; ++e) {
        float a  = __ldg(wm + e);
        float4 b = __ldg((const float4*)(We + (size_t)e * HDIM) + tid);
        acc.x = fmaf(a, b.x, acc.x);
        acc.y = fmaf(a, b.y, acc.y);
        acc.z = fmaf(a, b.z, acc.z);
        acc.w = fmaf(a, b.w, acc.w);
        cacc  = fmaf(a, __ldg(be + e), cacc);
    }
    ((float4*)(g_Whh + (size_t)i * 512))[tid] = acc;
    if (tid == 0) g_c[i] = cacc;
}

// ---------------------------------------------------------------------------
// Kernel 1: stage U[t] into out[t] for t in [t0, t0+1024):
//   t>0 : U = x_t @ Wx^T + b_ih + c       (c folds be @ Wm^T; m-lag substitution)
//   t==0: U = x_0 @ Wx^T + m_0 @ Wm^T + b_ih   (full pre-activation)
// CTA tile: 32 rows x 64 cols, K=256 per pass.  256 thr = 16 colg x 16 kg.
// Launched twice (t0=0, t0=1024) so rnn_seq is the 4th launch (ncu capture).
// ---------------------------------------------------------------------------
__global__ void __launch_bounds__(256, 2)
precompute_u_kernel(const float* __restrict__ x,
                    const float* __restrict__ m0,
                    const float* __restrict__ Wih,
                    const float* __restrict__ bih,
                    float* __restrict__ out, int t0) {
    extern __shared__ float sm1[];
    float* act  = sm1;                 // [32][256]
    float* part = sm1 + 32 * 256;      // [8 rows][8 ksets][64 cols]

    const int tid = threadIdx.x;
    const int cg  = tid & 15;
    const int kg  = tid >> 4;
    const int t   = blockIdx.y + t0;
    const int colt = blockIdx.x & 7, rowg = blockIdx.x >> 3;
    const int colbase = colt * 64, rowbase = rowg * 32;

    float sreg[8];
    #pragma unroll
    for (int i = 0; i < 8; ++i) sreg[i] = 0.f;

    const int npass = (t == 0) ? 2 : 1;
    for (int pass = 0; pass < npass; ++pass) {
        ull w[4][8];
        const int koff = pass ? IDIM : 0;
        #pragma unroll
        for (int c = 0; c < 4; ++c) {
            const ulonglong2* wp = (const ulonglong2*)
                (Wih + (size_t)(colbase + cg * 4 + c) * 512 + koff + kg * 16);
            #pragma unroll
            for (int j2 = 0; j2 < 4; ++j2) {
                ulonglong2 v = wp[j2];
                w[c][2 * j2]     = v.x;
                w[c][2 * j2 + 1] = v.y;
            }
        }
        const float* src = pass ? (m0 + (size_t)rowbase * EDIM)
                                : (x + ((size_t)t * BATCH + rowbase) * IDIM);
        __syncthreads();
        #pragma unroll
        for (int i = 0; i < 8; ++i)
            ((float4*)act)[tid + i * 256] = __ldg((const float4*)src + tid + i * 256);
        __syncthreads();

        for (int chunk = 0; chunk < 4; ++chunk) {
            #pragma unroll
            for (int b = 0; b < 8; ++b) {
                const ulonglong2* ap =
                    (const ulonglong2*)(act + (chunk * 8 + b) * 256 + kg * 16);
                ull acc[4] = {0ull, 0ull, 0ull, 0ull};
                #pragma unroll
                for (int j2 = 0; j2 < 4; ++j2) {
                    ulonglong2 v = ap[j2];
                    #pragma unroll
                    for (int c = 0; c < 4; ++c) {
                        acc[c] = ffma2(w[c][2 * j2],     v.x, acc[c]);
                        acc[c] = ffma2(w[c][2 * j2 + 1], v.y, acc[c]);
                    }
                }
                float4 r; float2 f;
                f = unpack2(acc[0]); r.x = f.x + f.y;
                f = unpack2(acc[1]); r.y = f.x + f.y;
                f = unpack2(acc[2]); r.z = f.x + f.y;
                f = unpack2(acc[3]); r.w = f.x + f.y;
                r.x += __shfl_xor_sync(0xffffffffu, r.x, 16);
                r.y += __shfl_xor_sync(0xffffffffu, r.y, 16);
                r.z += __shfl_xor_sync(0xffffffffu, r.z, 16);
                r.w += __shfl_xor_sync(0xffffffffu, r.w, 16);
                if (!(kg & 1))
                    ((float4*)part)[(b * 8 + (kg >> 1)) * 16 + cg] = r;
            }
            __syncthreads();
            #pragma unroll
            for (int h = 0; h < 2; ++h) {
                int o = tid + h * 256;
                int r = o >> 6, cc = o & 63;
                float s = 0.f;
                #pragma unroll
                for (int k = 0; k < 8; ++k) s += part[(r * 8 + k) * 64 + cc];
                sreg[chunk * 2 + h] += s;
            }
            __syncthreads();
        }
    }
    #pragma unroll
    for (int chunk = 0; chunk < 4; ++chunk) {
        #pragma unroll
        for (int h = 0; h < 2; ++h) {
            int o = tid + h * 256;
            int r = o >> 6, cc = o & 63;
            int col = colbase + cc;
            float bias = __ldg(bih + col) + ((t > 0) ? g_c[col] : 0.f);
            out[(size_t)t * BH + (size_t)(rowbase + chunk * 8 + r) * HDIM + col]
                = sreg[chunk * 2 + h] + bias;
        }
    }
}

// ---------------------------------------------------------------------------
// Kernel 2: sequential recurrence, 1024 supersteps + fused tails.
//   H[t] = tanh(U[t] + H[t-2] @ W_hh^T);  t=1 lags on h0; t=0 is pure tanh(U).
// 16 independent 8-CTA clusters: cluster = (parity, batch-group-of-8).
// CTA: 8 rows x 64 cols, K=512.  256 thr = 16 colg (RC=4) x 16 kg (KT=32).
//   (255-reg cap at 256 thr: 128 weight regs + working set fit, no spills.)
// H[t] overwrites U[t] in-place in `out`. Sync = barrier.cluster (rel/acq);
// next-U prefetch in the arrive->wait gap; no post-wait syncthreads needed.
// ---------------------------------------------------------------------------
__global__ void __launch_bounds__(256, 1) __cluster_dims__(8, 1, 1)
rnn_seq_kernel(const float* __restrict__ h0,
               const float* __restrict__ We,
               const float* __restrict__ be,
               float* __restrict__ out, int write_ht, int write_mt) {
    __shared__ float act [8 * 512];        // 16KB
    __shared__ float part[8 * 8 * 64];     // 16KB

    const int tid = threadIdx.x;
    const int cg  = tid & 15;
    const int kg  = tid >> 4;
    const int colt = blockIdx.x;           // 0..7 = cluster rank
    const int grp  = blockIdx.y;           // 0..15
    const int p    = grp >> 3;             // parity
    const int b0   = (grp & 7) * 8;        // batch base
    const int colbase = colt * 64;

    // W_hh slice: 4 cols x 32 k = 64 ull, reused 1024x.
    ull w[4][16];
    #pragma unroll
    for (int c = 0; c < 4; ++c) {
        const ulonglong2* wp = (const ulonglong2*)
            (g_Whh + (size_t)(colbase + cg * 4 + c) * 512 + kg * 32);
        #pragma unroll
        for (int j2 = 0; j2 < 8; ++j2) {
            ulonglong2 v = wp[j2];
            w[c][2 * j2]     = v.x;
            w[c][2 * j2 + 1] = v.y;
        }
    }

    const int o0 = tid, o1 = tid + 256;
    const int r0 = o0 >> 6, c0 = o0 & 63, r1 = o1 >> 6, c1 = o1 & 63;
    const size_t a0 = (size_t)(b0 + r0) * HDIM + colbase + c0;
    const size_t a1 = (size_t)(b0 + r1) * HDIM + colbase + c1;

    int t = p;
    float u0 = out[(size_t)t * BH + a0];   // prefetch U[t]
    float u1 = out[(size_t)t * BH + a1];

    for (int s = 0; s < 1024; ++s, t += 2) {
        const bool do_gemm = (s > 0) || (p == 1);
        if (do_gemm) {
            // stage lagged H (8 rows x 512): peers wrote it last superstep (L2)
            const float* src = (s == 0) ? (h0 + (size_t)b0 * HDIM)
                                        : (out + (size_t)(t - 2) * BH + (size_t)b0 * HDIM);
            ((float4*)act)[tid]       = __ldcg((const float4*)src + tid);
            ((float4*)act)[tid + 256] = __ldcg((const float4*)src + tid + 256);
            ((float4*)act)[tid + 512] = __ldcg((const float4*)src + tid + 512);
            ((float4*)act)[tid + 768] = __ldcg((const float4*)src + tid + 768);
            __syncthreads();

            #pragma unroll
            for (int b = 0; b < 8; ++b) {
                const ulonglong2* ap = (const ulonglong2*)(act + b * 512 + kg * 32);
                ull acc[4] = {0ull, 0ull, 0ull, 0ull};
                #pragma unroll
                for (int j2 = 0; j2 < 8; ++j2) {
                    ulonglong2 v = ap[j2];
                    #pragma unroll
                    for (int c = 0; c < 4; ++c) {
                        acc[c] = ffma2(w[c][2 * j2],     v.x, acc[c]);
                        acc[c] = ffma2(w[c][2 * j2 + 1], v.y, acc[c]);
                    }
                }
                float4 r; float2 f;
                f = unpack2(acc[0]); r.x = f.x + f.y;
                f = unpack2(acc[1]); r.y = f.x + f.y;
                f = unpack2(acc[2]); r.z = f.x + f.y;
                f = unpack2(acc[3]); r.w = f.x + f.y;
                r.x += __shfl_xor_sync(0xffffffffu, r.x, 16);
                r.y += __shfl_xor_sync(0xffffffffu, r.y, 16);
                r.z += __shfl_xor_sync(0xffffffffu, r.z, 16);
                r.w += __shfl_xor_sync(0xffffffffu, r.w, 16);
                if (!(kg & 1))
                    ((float4*)part)[(b * 8 + (kg >> 1)) * 16 + cg] = r;
            }
            __syncthreads();
        }

        float s0 = u0, s1 = u1;
        if (do_gemm) {
            #pragma unroll
            for (int k = 0; k < 8; ++k) {
                s0 += part[(r0 * 8 + k) * 64 + c0];
                s1 += part[(r1 * 8 + k) * 64 + c1];
            }
        }
        float hv0 = fast_tanh(s0);
        float hv1 = fast_tanh(s1);
        float* dst = out + (size_t)t * BH;
        dst[a0] = hv0;
        dst[a1] = hv1;
        if (p == 1 && s == 1023 && write_ht) {   // h_T = H[2047]
            out[(size_t)SQ * BH + a0] = hv0;
            out[(size_t)SQ * BH + a1] = hv1;
        }

        // cluster barrier: release H[t]; prefetch U[t+2] in the gap; acquire.
        asm volatile("barrier.cluster.arrive.aligned;" ::: "memory");
        if (s < 1023) {
            u0 = out[(size_t)(t + 2) * BH + a0];
            u1 = out[(size_t)(t + 2) * BH + a1];
        }
        asm volatile("barrier.cluster.wait.aligned;" ::: "memory");
        // no extra __syncthreads: cluster barrier subsumes the CTA barrier
    }

    // m_T = H[2046] @ We^T + be  (parity-0 clusters; H[2046] visible post-barrier)
    if (p == 0 && write_mt) {
        const float* src = out + (size_t)(SQ - 2) * BH + (size_t)b0 * HDIM;
        ((float4*)act)[tid]       = __ldcg((const float4*)src + tid);
        ((float4*)act)[tid + 256] = __ldcg((const float4*)src + tid + 256);
        ((float4*)act)[tid + 512] = __ldcg((const float4*)src + tid + 512);
        ((float4*)act)[tid + 768] = __ldcg((const float4*)src + tid + 768);
        __syncthreads();
        {
            int b = tid >> 5, e = colt * 32 + (tid & 31);   // 8 rows x 32 e-cols
            float acc = __ldg(be + e);
            const float4* wr = (const float4*)(We + (size_t)e * HDIM);
            const float* hp = act + b * 512;
            #pragma unroll 8
            for (int j4 = 0; j4 < 128; ++j4) {
                float4 wv = __ldg(wr + j4);
                acc = fmaf(wv.x, hp[j4 * 4 + 0], acc);
                acc = fmaf(wv.y, hp[j4 * 4 + 1], acc);
                acc = fmaf(wv.z, hp[j4 * 4 + 2], acc);
                acc = fmaf(wv.w, hp[j4 * 4 + 3], acc);
            }
            out[(size_t)SQ * BH + (size_t)BATCH * HDIM
                + (size_t)(b0 + b) * EDIM + e] = acc;
        }
    }
}

extern "C" void kernel_launch(void* const* d_in, const int* in_sizes, int n_in,
                              void* d_out, int out_size) {
    const float* x   = (const float*)d_in[0];  // input_seq [S,B,I]
    const float* h0  = (const float*)d_in[1];  // h_0 [B,H]
    const float* m0  = (const float*)d_in[2];  // m_0 [B,E]
    const float* We  = (const float*)d_in[3];  // W_embed [E,H]
    const float* be  = (const float*)d_in[4];  // b_embed [E]
    const float* Wih = (const float*)d_in[5];  // W_ih [H,I+E]
    const float* bih = (const float*)d_in[6];  // b_ih [H]
    float* out = (float*)d_out;

    long long seq_elems = (long long)SQ * BH;
    int write_ht = (out_size >= seq_elems + (long long)BATCH * HDIM) ? 1 : 0;
    int write_mt = (out_size >= seq_elems + (long long)BATCH * HDIM
                                + (long long)BATCH * EDIM) ? 1 : 0;

    // 0) W_hh = Wm @ We, c = Wm @ be
    prep_whh_kernel<<<HDIM, 128>>>(Wih, We, be);
    // 1+2) U[t] -> out[t], split in two so rnn_seq is the 4th launch (ncu -s)
    precompute_u_kernel<<<dim3(16, 1024), 256, 49152>>>(x, m0, Wih, bih, out, 0);
    precompute_u_kernel<<<dim3(16, 1024), 256, 49152>>>(x, m0, Wih, bih, out, 1024);
    // 3) recurrence: 16 independent 8-CTA clusters, 1024 supersteps (+tails)
    rnn_seq_kernel<<<dim3(8, 16), 256>>>(h0, We, be, out, write_ht, write_mt);
}